// round 6
// baseline (speedup 1.0000x reference)
#include <cuda_runtime.h>
#include <math.h>

#define BLOCK_THREADS 128
#define DIRS_PER_THREAD 2
#define DIRS_PER_BLOCK (BLOCK_THREADS * DIRS_PER_THREAD)
#define MAX_COMP 64

typedef unsigned long long u64;

__device__ __forceinline__ u64 pk2(float lo, float hi) {
    u64 r; asm("mov.b64 %0, {%1, %2};" : "=l"(r) : "f"(lo), "f"(hi)); return r;
}
__device__ __forceinline__ void unpk2(u64 v, float& lo, float& hi) {
    asm("mov.b64 {%0, %1}, %2;" : "=f"(lo), "=f"(hi) : "l"(v));
}
__device__ __forceinline__ u64 ffma2(u64 a, u64 b, u64 c) {
    u64 r; asm("fma.rn.f32x2 %0, %1, %2, %3;" : "=l"(r) : "l"(a), "l"(b), "l"(c)); return r;
}
__device__ __forceinline__ u64 fadd2(u64 a, u64 b) {
    u64 r; asm("add.rn.f32x2 %0, %1, %2;" : "=l"(r) : "l"(a), "l"(b)); return r;
}
__device__ __forceinline__ u64 fsub2(u64 a, u64 b) {
    u64 r; asm("sub.rn.f32x2 %0, %1, %2;" : "=l"(r) : "l"(a), "l"(b)); return r;
}
__device__ __forceinline__ float ex2a(float x) {
    float r; asm("ex2.approx.ftz.f32 %0, %1;" : "=f"(r) : "f"(x)); return r;
}

__global__ void __launch_bounds__(BLOCK_THREADS, 12)
vmf_mixture_kernel(const float* __restrict__ lambdas,
                   const float* __restrict__ kappas,
                   const float* __restrict__ thetas,
                   const float* __restrict__ phis,
                   const float* __restrict__ wi,
                   float* __restrict__ out,
                   int S, int N)
{
    // per component: [0]={ {ax,ax},{ay,ay} }  [1]={ {az,az},{b,b} }  (pre-broadcast f32x2)
    __shared__ ulonglong2 sPK[MAX_COMP][2];

    int t = threadIdx.x;
    if (t < N) {
        float kappa = kappas[t];
        float lam   = lambdas[t];
        float th    = thetas[t];
        float ph    = phis[t];

        float st = sinf(th), ct = cosf(th);
        float sp = sinf(ph), cp = cosf(ph);

        float k = fmaxf(kappa, 1e-8f);
        float norm = (kappa < 1e-5f)
                   ? 0.07957747154594767f                       // 1/(4pi)
                   : k * 0.15915494309189535f / (1.0f - expf(-2.0f * k));
        float c = lam * norm;                                   // > 0 always

        const float LOG2E = 1.4426950408889634f;
        float a  = kappa * LOG2E;
        float b  = log2f(c) - a;                                // fold weight into exponent
        float ax = a * (st * cp), ay = a * (st * sp), az = a * ct;

        sPK[t][0] = make_ulonglong2(pk2(ax, ax), pk2(ay, ay));
        sPK[t][1] = make_ulonglong2(pk2(az, az), pk2(b,  b));
    }
    __syncthreads();

    int base = blockIdx.x * DIRS_PER_BLOCK + t;

    u64 X0, Y0, Z0;
    u64 ACC = 0ull;
    {
        int i0 = base;
        int i1 = base + BLOCK_THREADS;
        int o0 = (i0 < S) ? 3 * i0 : 0;
        int o1 = (i1 < S) ? 3 * i1 : 0;
        X0 = pk2(wi[o0 + 0], wi[o1 + 0]);
        Y0 = pk2(wi[o0 + 1], wi[o1 + 1]);
        Z0 = pk2(wi[o0 + 2], wi[o1 + 2]);
    }

    // packed constants for software exp2 (registers, loop invariant)
    const u64 MAGIC2 = pk2(12582912.0f, 12582912.0f);      // 1.5*2^23 round-to-int magic
    const u64 C0_2 = pk2(1.0f,                  1.0f);
    const u64 C1_2 = pk2(0.6931471805599453f,   0.6931471805599453f);
    const u64 C2_2 = pk2(0.2402265069591007f,   0.2402265069591007f);
    const u64 C3_2 = pk2(0.05550410866482158f,  0.05550410866482158f);
    const u64 C4_2 = pk2(0.009618129107628477f, 0.009618129107628477f);
    const int MCLAMP_BITS = __float_as_int(12582912.0f - 124.0f); // clamp n >= -124

    int NQ = N >> 2;                 // comp quads; N=64 -> 16
    #pragma unroll 4
    for (int i = 0; i < NQ; i++) {
        int n0 = 4 * i;
        ulonglong2 c0a = sPK[n0 + 0][0], c0b = sPK[n0 + 0][1];
        ulonglong2 c1a = sPK[n0 + 1][0], c1b = sPK[n0 + 1][1];
        ulonglong2 c2a = sPK[n0 + 2][0], c2b = sPK[n0 + 2][1];
        ulonglong2 c3a = sPK[n0 + 3][0], c3b = sPK[n0 + 3][1];

        // 4 packed dot+bias args (independent chains)
        u64 a0 = ffma2(c0a.x, X0, ffma2(c0a.y, Y0, ffma2(c0b.x, Z0, c0b.y)));
        u64 a1 = ffma2(c1a.x, X0, ffma2(c1a.y, Y0, ffma2(c1b.x, Z0, c1b.y)));
        u64 a2 = ffma2(c2a.x, X0, ffma2(c2a.y, Y0, ffma2(c2b.x, Z0, c2b.y)));
        u64 a3 = ffma2(c3a.x, X0, ffma2(c3a.y, Y0, ffma2(c3b.x, Z0, c3b.y)));

        float lo, hi;

        // comps n0..n0+2 via MUFU, packed accumulate
        unpk2(a0, lo, hi);
        ACC = fadd2(ACC, pk2(ex2a(lo), ex2a(hi)));
        unpk2(a1, lo, hi);
        ACC = fadd2(ACC, pk2(ex2a(lo), ex2a(hi)));
        unpk2(a2, lo, hi);
        ACC = fadd2(ACC, pk2(ex2a(lo), ex2a(hi)));

        // comp n0+3 via packed software exp2 on FMA/ALU pipes
        {
            u64 m2 = fadd2(a3, MAGIC2);         // m bits hold round(arg) + magic
            u64 n2 = fsub2(m2, MAGIC2);         // n = round(arg) as float
            u64 r2 = fsub2(a3, n2);             // r in [-0.5, 0.5]
            u64 q2 = ffma2(C4_2, r2, C3_2);     // poly(r) ~= 2^r
            q2 = ffma2(q2, r2, C2_2);
            q2 = ffma2(q2, r2, C1_2);
            q2 = ffma2(q2, r2, C0_2);

            float mlo, mhi, qlo, qhi;
            unpk2(m2, mlo, mhi);
            unpk2(q2, qlo, qhi);
            int il = max(__float_as_int(mlo), MCLAMP_BITS);
            int ih = max(__float_as_int(mhi), MCLAMP_BITS);
            // splice exponent: bits(poly) + (n << 23)  (exact mod 2^32)
            float elo = __int_as_float(__float_as_int(qlo) + (il << 23));
            float ehi = __int_as_float(__float_as_int(qhi) + (ih << 23));
            ACC = fadd2(ACC, pk2(elo, ehi));
        }
    }

    // N not multiple of 4 tail (not hit for N=64) — all MUFU
    for (int n = NQ << 2; n < N; n++) {
        ulonglong2 ca = sPK[n][0];
        ulonglong2 cb = sPK[n][1];
        float lo, hi;
        u64 a0 = ffma2(ca.x, X0, ffma2(ca.y, Y0, ffma2(cb.x, Z0, cb.y)));
        unpk2(a0, lo, hi);
        ACC = fadd2(ACC, pk2(ex2a(lo), ex2a(hi)));
    }

    {
        float a0, a1;
        unpk2(ACC, a0, a1);
        int i0 = base;
        int i1 = base + BLOCK_THREADS;
        if (i0 < S) out[i0] = a0;
        if (i1 < S) out[i1] = a1;
    }
}

extern "C" void kernel_launch(void* const* d_in, const int* in_sizes, int n_in,
                              void* d_out, int out_size)
{
    const float* lambdas = (const float*)d_in[0];
    const float* kappas  = (const float*)d_in[1];
    const float* thetas  = (const float*)d_in[2];
    const float* phis    = (const float*)d_in[3];
    const float* wi      = (const float*)d_in[4];
    float* out = (float*)d_out;

    int N = in_sizes[0];
    int S = in_sizes[4] / 3;

    int blocks = (S + DIRS_PER_BLOCK - 1) / DIRS_PER_BLOCK;
    vmf_mixture_kernel<<<blocks, BLOCK_THREADS>>>(lambdas, kappas, thetas, phis, wi,
                                                  out, S, N);
}

// round 7
// speedup vs baseline: 1.0115x; 1.0115x over previous
#include <cuda_runtime.h>
#include <math.h>

#define BLOCK_THREADS 64
#define DIRS_PER_THREAD 4
#define DIRS_PER_BLOCK (BLOCK_THREADS * DIRS_PER_THREAD)
#define MAX_COMP 64

typedef unsigned long long u64;

__device__ __forceinline__ u64 pk2(float lo, float hi) {
    u64 r; asm("mov.b64 %0, {%1, %2};" : "=l"(r) : "f"(lo), "f"(hi)); return r;
}
__device__ __forceinline__ void unpk2(u64 v, float& lo, float& hi) {
    asm("mov.b64 {%0, %1}, %2;" : "=f"(lo), "=f"(hi) : "l"(v));
}
__device__ __forceinline__ u64 ffma2(u64 a, u64 b, u64 c) {
    u64 r; asm("fma.rn.f32x2 %0, %1, %2, %3;" : "=l"(r) : "l"(a), "l"(b), "l"(c)); return r;
}
__device__ __forceinline__ u64 fadd2(u64 a, u64 b) {
    u64 r; asm("add.rn.f32x2 %0, %1, %2;" : "=l"(r) : "l"(a), "l"(b)); return r;
}
__device__ __forceinline__ u64 fsub2(u64 a, u64 b) {
    u64 r; asm("sub.rn.f32x2 %0, %1, %2;" : "=l"(r) : "l"(a), "l"(b)); return r;
}
__device__ __forceinline__ float ex2a(float x) {
    float r; asm("ex2.approx.ftz.f32 %0, %1;" : "=f"(r) : "f"(x)); return r;
}

__global__ void __launch_bounds__(BLOCK_THREADS, 24)
vmf_mixture_kernel(const float* __restrict__ lambdas,
                   const float* __restrict__ kappas,
                   const float* __restrict__ thetas,
                   const float* __restrict__ phis,
                   const float* __restrict__ wi,
                   float* __restrict__ out,
                   int S, int N)
{
    // per component: [0]={ {ax,ax},{ay,ay} }  [1]={ {az,az},{b,b} }  (pre-broadcast f32x2)
    __shared__ ulonglong2 sPK[MAX_COMP][2];

    int t = threadIdx.x;
    if (t < N) {
        float kappa = kappas[t];
        float lam   = lambdas[t];
        float th    = thetas[t];
        float ph    = phis[t];

        float st = sinf(th), ct = cosf(th);
        float sp = sinf(ph), cp = cosf(ph);

        float k = fmaxf(kappa, 1e-8f);
        float norm = (kappa < 1e-5f)
                   ? 0.07957747154594767f                       // 1/(4pi)
                   : k * 0.15915494309189535f / (1.0f - expf(-2.0f * k));
        float c = lam * norm;                                   // > 0 always

        const float LOG2E = 1.4426950408889634f;
        float a  = kappa * LOG2E;
        float b  = log2f(c) - a;                                // fold weight into exponent
        float ax = a * (st * cp), ay = a * (st * sp), az = a * ct;

        sPK[t][0] = make_ulonglong2(pk2(ax, ax), pk2(ay, ay));
        sPK[t][1] = make_ulonglong2(pk2(az, az), pk2(b,  b));
    }
    __syncthreads();

    int base = blockIdx.x * DIRS_PER_BLOCK + t;

    u64 X0, Y0, Z0, X1, Y1, Z1;
    u64 ACC0 = 0ull, ACC1 = 0ull;
    {
        int i0 = base;
        int i1 = base + BLOCK_THREADS;
        int i2 = base + 2 * BLOCK_THREADS;
        int i3 = base + 3 * BLOCK_THREADS;
        int o0 = (i0 < S) ? 3 * i0 : 0;
        int o1 = (i1 < S) ? 3 * i1 : 0;
        int o2 = (i2 < S) ? 3 * i2 : 0;
        int o3 = (i3 < S) ? 3 * i3 : 0;
        X0 = pk2(wi[o0 + 0], wi[o1 + 0]);
        Y0 = pk2(wi[o0 + 1], wi[o1 + 1]);
        Z0 = pk2(wi[o0 + 2], wi[o1 + 2]);
        X1 = pk2(wi[o2 + 0], wi[o3 + 0]);
        Y1 = pk2(wi[o2 + 1], wi[o3 + 1]);
        Z1 = pk2(wi[o2 + 2], wi[o3 + 2]);
    }

    // packed constants for software exp2 (registers, loop invariant)
    // degree-3 minimax poly for 2^r on [-0.5, 0.5]  (rel err ~1e-4)
    const u64 MAGIC2 = pk2(12582912.0f, 12582912.0f);      // 1.5*2^23 round-to-int magic
    const u64 C0_2 = pk2(0.9999925290940403f,  0.9999925290940403f);
    const u64 C1_2 = pk2(0.6931530732006839f,  0.6931530732006839f);
    const u64 C2_2 = pk2(0.2401536840127826f,  0.2401536840127826f);
    const u64 C3_2 = pk2(0.0558263180375376f,  0.0558263180375376f);
    const int MCLAMP_BITS = __float_as_int(12582912.0f - 124.0f); // clamp n >= -124

    int NH = N >> 1;
    #pragma unroll 2
    for (int i = 0; i < NH; i++) {
        int n0 = 2 * i, n1 = 2 * i + 1;
        ulonglong2 c0a = sPK[n0][0];   // {ax, ay}
        ulonglong2 c0b = sPK[n0][1];   // {az, b }
        ulonglong2 c1a = sPK[n1][0];
        ulonglong2 c1b = sPK[n1][1];

        // 4 packed dot+bias args (independent chains)
        u64 a00 = ffma2(c0a.x, X0, ffma2(c0a.y, Y0, ffma2(c0b.x, Z0, c0b.y)));
        u64 a01 = ffma2(c0a.x, X1, ffma2(c0a.y, Y1, ffma2(c0b.x, Z1, c0b.y)));
        u64 a10 = ffma2(c1a.x, X0, ffma2(c1a.y, Y0, ffma2(c1b.x, Z0, c1b.y)));
        u64 a11 = ffma2(c1a.x, X1, ffma2(c1a.y, Y1, ffma2(c1b.x, Z1, c1b.y)));

        float lo, hi;

        // 3 pairs via MUFU, packed accumulate
        unpk2(a00, lo, hi);
        ACC0 = fadd2(ACC0, pk2(ex2a(lo), ex2a(hi)));
        unpk2(a01, lo, hi);
        ACC1 = fadd2(ACC1, pk2(ex2a(lo), ex2a(hi)));
        unpk2(a10, lo, hi);
        ACC0 = fadd2(ACC0, pk2(ex2a(lo), ex2a(hi)));

        // 1 pair via packed software exp2 on FMA/ALU pipes
        {
            u64 m2 = fadd2(a11, MAGIC2);        // m bits hold round(arg) + magic
            u64 n2 = fsub2(m2, MAGIC2);         // n = round(arg) as float
            u64 r2 = fsub2(a11, n2);            // r in [-0.5, 0.5]
            u64 q2 = ffma2(C3_2, r2, C2_2);     // poly(r) ~= 2^r (deg 3)
            q2 = ffma2(q2, r2, C1_2);
            q2 = ffma2(q2, r2, C0_2);

            float mlo, mhi, qlo, qhi;
            unpk2(m2, mlo, mhi);
            unpk2(q2, qlo, qhi);
            int il = max(__float_as_int(mlo), MCLAMP_BITS);
            int ih = max(__float_as_int(mhi), MCLAMP_BITS);
            // splice exponent: bits(poly) + (n << 23)  (exact mod 2^32)
            float elo = __int_as_float(__float_as_int(qlo) + (il << 23));
            float ehi = __int_as_float(__float_as_int(qhi) + (ih << 23));
            ACC1 = fadd2(ACC1, pk2(elo, ehi));
        }
    }

    // odd-N tail (not hit for N=64) — all MUFU
    if (N & 1) {
        int n0 = N - 1;
        ulonglong2 ca = sPK[n0][0];
        ulonglong2 cb = sPK[n0][1];
        float lo, hi;
        u64 a0 = ffma2(ca.x, X0, ffma2(ca.y, Y0, ffma2(cb.x, Z0, cb.y)));
        u64 a1 = ffma2(ca.x, X1, ffma2(ca.y, Y1, ffma2(cb.x, Z1, cb.y)));
        unpk2(a0, lo, hi); ACC0 = fadd2(ACC0, pk2(ex2a(lo), ex2a(hi)));
        unpk2(a1, lo, hi); ACC1 = fadd2(ACC1, pk2(ex2a(lo), ex2a(hi)));
    }

    {
        float a0, a1, a2, a3;
        unpk2(ACC0, a0, a1);
        unpk2(ACC1, a2, a3);
        int i0 = base;
        int i1 = base + BLOCK_THREADS;
        int i2 = base + 2 * BLOCK_THREADS;
        int i3 = base + 3 * BLOCK_THREADS;
        if (i0 < S) out[i0] = a0;
        if (i1 < S) out[i1] = a1;
        if (i2 < S) out[i2] = a2;
        if (i3 < S) out[i3] = a3;
    }
}

extern "C" void kernel_launch(void* const* d_in, const int* in_sizes, int n_in,
                              void* d_out, int out_size)
{
    const float* lambdas = (const float*)d_in[0];
    const float* kappas  = (const float*)d_in[1];
    const float* thetas  = (const float*)d_in[2];
    const float* phis    = (const float*)d_in[3];
    const float* wi      = (const float*)d_in[4];
    float* out = (float*)d_out;

    int N = in_sizes[0];
    int S = in_sizes[4] / 3;

    int blocks = (S + DIRS_PER_BLOCK - 1) / DIRS_PER_BLOCK;
    vmf_mixture_kernel<<<blocks, BLOCK_THREADS>>>(lambdas, kappas, thetas, phis, wi,
                                                  out, S, N);
}

// round 8
// speedup vs baseline: 1.1926x; 1.1791x over previous
#include <cuda_runtime.h>
#include <math.h>

#define BLOCK_THREADS 128
#define DIRS_PER_THREAD 2
#define DIRS_PER_BLOCK (BLOCK_THREADS * DIRS_PER_THREAD)
#define MAX_COMP 64

__device__ __forceinline__ float ex2a(float x) {
    float r; asm("ex2.approx.ftz.f32 %0, %1;" : "=f"(r) : "f"(x)); return r;
}

__global__ void __launch_bounds__(BLOCK_THREADS, 16)
vmf_mixture_kernel(const float* __restrict__ lambdas,
                   const float* __restrict__ kappas,
                   const float* __restrict__ thetas,
                   const float* __restrict__ phis,
                   const float* __restrict__ wi,
                   float* __restrict__ out,
                   int S, int N)
{
    // per component: {ax, ay, az, b} with a = kappa*log2e folded into mu,
    // b = log2(lambda*norm) - a  (weight folded into the exponent)
    __shared__ float4 sC[MAX_COMP];

    int t = threadIdx.x;
    if (t < N) {
        float kappa = kappas[t];
        float lam   = lambdas[t];
        float th    = thetas[t];
        float ph    = phis[t];

        float st = sinf(th), ct = cosf(th);
        float sp = sinf(ph), cp = cosf(ph);

        float k = fmaxf(kappa, 1e-8f);
        float norm = (kappa < 1e-5f)
                   ? 0.07957747154594767f                       // 1/(4pi)
                   : k * 0.15915494309189535f / (1.0f - expf(-2.0f * k));
        float c = lam * norm;                                   // > 0 always

        const float LOG2E = 1.4426950408889634f;
        float a = kappa * LOG2E;
        float b = log2f(c) - a;
        sC[t] = make_float4(a * (st * cp), a * (st * sp), a * ct, b);
    }
    __syncthreads();

    int base = blockIdx.x * DIRS_PER_BLOCK + t;

    int i0 = base;
    int i1 = base + BLOCK_THREADS;
    int o0 = (i0 < S) ? 3 * i0 : 0;
    int o1 = (i1 < S) ? 3 * i1 : 0;
    float x0 = wi[o0 + 0], y0 = wi[o0 + 1], z0 = wi[o0 + 2];
    float x1 = wi[o1 + 0], y1 = wi[o1 + 1], z1 = wi[o1 + 2];

    float acc0 = 0.0f, acc1 = 0.0f;

    #pragma unroll 4
    for (int n = 0; n < N; n++) {
        float4 c = sC[n];
        float a0 = fmaf(c.x, x0, fmaf(c.y, y0, fmaf(c.z, z0, c.w)));
        float a1 = fmaf(c.x, x1, fmaf(c.y, y1, fmaf(c.z, z1, c.w)));
        acc0 += ex2a(a0);
        acc1 += ex2a(a1);
    }

    if (i0 < S) out[i0] = acc0;
    if (i1 < S) out[i1] = acc1;
}

extern "C" void kernel_launch(void* const* d_in, const int* in_sizes, int n_in,
                              void* d_out, int out_size)
{
    const float* lambdas = (const float*)d_in[0];
    const float* kappas  = (const float*)d_in[1];
    const float* thetas  = (const float*)d_in[2];
    const float* phis    = (const float*)d_in[3];
    const float* wi      = (const float*)d_in[4];
    float* out = (float*)d_out;

    int N = in_sizes[0];
    int S = in_sizes[4] / 3;

    int blocks = (S + DIRS_PER_BLOCK - 1) / DIRS_PER_BLOCK;
    vmf_mixture_kernel<<<blocks, BLOCK_THREADS>>>(lambdas, kappas, thetas, phis, wi,
                                                  out, S, N);
}